// round 1
// baseline (speedup 1.0000x reference)
#include <cuda_runtime.h>
#include <cuda_bf16.h>
#include <cstdint>

// Problem: out[b,m,c] = sum_{k<3} vals[m,k] * x[b, cols[m,k], c]
//   x:    [B=8, N=50000, C=128] float32
//   cols: [M=25000, K=3] int32
//   vals: [M=25000, K=3] float32
//   out:  [B=8, M=25000, C=128] float32
//
// One warp per (b, m): 32 lanes x float4 = 128 floats = one C-row.
// All loads/stores are fully coalesced 512B row transactions.

#define B_DIM 8
#define N_DIM 50000
#define C_DIM 128
#define M_DIM 25000
#define C_VEC 32          // C_DIM / 4 float4 per row

__global__ __launch_bounds__(256)
void mesh_sampling_kernel(const float4* __restrict__ x,
                          const int*    __restrict__ cols,
                          const float*  __restrict__ vals,
                          float4*       __restrict__ out)
{
    const int gwarp = (blockIdx.x * blockDim.x + threadIdx.x) >> 5;
    const int lane  = threadIdx.x & 31;
    if (gwarp >= B_DIM * M_DIM) return;

    const int b = gwarp / M_DIM;
    const int m = gwarp - b * M_DIM;

    // 3 indices + 3 weights for this m (warp-uniform; broadcast load)
    const int  c0 = __ldg(cols + m * 3 + 0);
    const int  c1 = __ldg(cols + m * 3 + 1);
    const int  c2 = __ldg(cols + m * 3 + 2);
    const float v0 = __ldg(vals + m * 3 + 0);
    const float v1 = __ldg(vals + m * 3 + 1);
    const float v2 = __ldg(vals + m * 3 + 2);

    const float4* xb = x + (size_t)b * N_DIM * C_VEC;

    // Three independent 16B loads per lane -> MLP=3, coalesced 512B rows.
    const float4 a0 = __ldg(xb + (size_t)c0 * C_VEC + lane);
    const float4 a1 = __ldg(xb + (size_t)c1 * C_VEC + lane);
    const float4 a2 = __ldg(xb + (size_t)c2 * C_VEC + lane);

    float4 r;
    r.x = v0 * a0.x + v1 * a1.x + v2 * a2.x;
    r.y = v0 * a0.y + v1 * a1.y + v2 * a2.y;
    r.z = v0 * a0.z + v1 * a1.z + v2 * a2.z;
    r.w = v0 * a0.w + v1 * a1.w + v2 * a2.w;

    out[(size_t)gwarp * C_VEC + lane] = r;
}

extern "C" void kernel_launch(void* const* d_in, const int* in_sizes, int n_in,
                              void* d_out, int out_size)
{
    const float4* x    = (const float4*)d_in[0];
    const int*    cols = (const int*)d_in[1];
    const float*  vals = (const float*)d_in[2];
    float4*       out  = (float4*)d_out;

    const int total_warps   = B_DIM * M_DIM;          // 200000
    const int threads       = 256;                    // 8 warps / block
    const int warps_per_blk = threads / 32;
    const int blocks        = (total_warps + warps_per_blk - 1) / warps_per_blk;

    mesh_sampling_kernel<<<blocks, threads>>>(x, cols, vals, out);
}

// round 2
// speedup vs baseline: 1.0334x; 1.0334x over previous
#include <cuda_runtime.h>
#include <cuda_bf16.h>
#include <cstdint>

// out[b,m,c] = sum_{k<3} vals[m,k] * x[b, cols[m,k], c]
//   x: [8, 50000, 128] f32   cols: [25000, 3] i32   vals: [25000, 3] f32
//   out: [8, 25000, 128] f32
//
// One warp handles one m for TWO batches (2bp, 2bp+1):
//  - 6 independent coalesced LDG.128 per lane (MLP=6) hides DRAM latency
//  - cols/vals loaded once per warp for both batches
//  - output written with streaming stores (evict-first) so L2 stays
//    dedicated to the x batch slices (gather reuse factor ~1.93x)

#define B_DIM 8
#define N_DIM 50000
#define M_DIM 25000
#define C_VEC 32              // 128 floats / 4 per float4
#define BP    (B_DIM / 2)     // batch pairs = 4

__device__ __forceinline__ void stcs(float4* p, float4 v) {
    asm volatile("st.global.cs.v4.f32 [%0], {%1,%2,%3,%4};"
                 :: "l"(p), "f"(v.x), "f"(v.y), "f"(v.z), "f"(v.w));
}

__global__ __launch_bounds__(256)
void mesh_sampling_kernel(const float4* __restrict__ x,
                          const int*    __restrict__ cols,
                          const float*  __restrict__ vals,
                          float4*       __restrict__ out)
{
    const int gwarp = (blockIdx.x * blockDim.x + threadIdx.x) >> 5;
    const int lane  = threadIdx.x & 31;
    if (gwarp >= BP * M_DIM) return;

    const int bp = gwarp / M_DIM;        // batch pair 0..3
    const int m  = gwarp - bp * M_DIM;
    const int b0 = bp * 2;
    const int b1 = b0 + 1;

    // warp-uniform indices / weights (broadcast loads, L2-resident)
    const int  c0 = __ldg(cols + m * 3 + 0);
    const int  c1 = __ldg(cols + m * 3 + 1);
    const int  c2 = __ldg(cols + m * 3 + 2);
    const float v0 = __ldg(vals + m * 3 + 0);
    const float v1 = __ldg(vals + m * 3 + 1);
    const float v2 = __ldg(vals + m * 3 + 2);

    const float4* xb0 = x + (size_t)b0 * N_DIM * C_VEC;
    const float4* xb1 = x + (size_t)b1 * N_DIM * C_VEC;

    // 6 independent 16B loads in flight (MLP=6), all 512B-row coalesced
    const float4 a0 = __ldg(xb0 + (size_t)c0 * C_VEC + lane);
    const float4 a1 = __ldg(xb0 + (size_t)c1 * C_VEC + lane);
    const float4 a2 = __ldg(xb0 + (size_t)c2 * C_VEC + lane);
    const float4 a3 = __ldg(xb1 + (size_t)c0 * C_VEC + lane);
    const float4 a4 = __ldg(xb1 + (size_t)c1 * C_VEC + lane);
    const float4 a5 = __ldg(xb1 + (size_t)c2 * C_VEC + lane);

    float4 r0, r1;
    r0.x = v0 * a0.x + v1 * a1.x + v2 * a2.x;
    r0.y = v0 * a0.y + v1 * a1.y + v2 * a2.y;
    r0.z = v0 * a0.z + v1 * a1.z + v2 * a2.z;
    r0.w = v0 * a0.w + v1 * a1.w + v2 * a2.w;

    r1.x = v0 * a3.x + v1 * a4.x + v2 * a5.x;
    r1.y = v0 * a3.y + v1 * a4.y + v2 * a5.y;
    r1.z = v0 * a3.z + v1 * a4.z + v2 * a5.z;
    r1.w = v0 * a3.w + v1 * a4.w + v2 * a5.w;

    // streaming stores: output is write-once, keep it out of L2
    stcs(out + ((size_t)b0 * M_DIM + m) * C_VEC + lane, r0);
    stcs(out + ((size_t)b1 * M_DIM + m) * C_VEC + lane, r1);
}

extern "C" void kernel_launch(void* const* d_in, const int* in_sizes, int n_in,
                              void* d_out, int out_size)
{
    const float4* x    = (const float4*)d_in[0];
    const int*    cols = (const int*)d_in[1];
    const float*  vals = (const float*)d_in[2];
    float4*       out  = (float4*)d_out;

    const int total_warps   = BP * M_DIM;             // 100000
    const int threads       = 256;                    // 8 warps / block
    const int warps_per_blk = threads / 32;
    const int blocks        = (total_warps + warps_per_blk - 1) / warps_per_blk;

    mesh_sampling_kernel<<<blocks, threads>>>(x, cols, vals, out);
}

// round 5
// speedup vs baseline: 1.0402x; 1.0066x over previous
#include <cuda_runtime.h>
#include <cuda_bf16.h>
#include <cstdint>

// out[b,m,c] = sum_{k<3} vals[m,k] * x[b, cols[m,k], c]
//   x: [8, 50000, 128] f32   cols: [25000, 3] i32   vals: [25000, 3] f32
//   out: [8, 25000, 128] f32
//
// One warp handles TWO m-values for TWO batches: 12 independent coalesced
// LDG.128 per lane (MLP=12) to drive DRAM utilization. Only 2 batch slices
// are L2-active at once so the ~1.93x gather reuse keeps hitting in L2.
// Output uses streaming .cs stores (write-once, evict-first) so the store
// stream doesn't displace the reused x lines.

#define B_DIM 8
#define N_DIM 50000
#define M_DIM 25000
#define C_VEC 32              // 128 floats / 4 per float4
#define BP    (B_DIM / 2)     // batch pairs = 4
#define MI    (M_DIM / 2)     // m pairs = 12500

__device__ __forceinline__ void stcs(float4* p, float4 v) {
    asm volatile("st.global.cs.v4.f32 [%0], {%1,%2,%3,%4};"
                 :: "l"(p), "f"(v.x), "f"(v.y), "f"(v.z), "f"(v.w));
}

__global__ __launch_bounds__(256, 3)
void mesh_sampling_kernel(const float4* __restrict__ x,
                          const int*    __restrict__ cols,
                          const float*  __restrict__ vals,
                          float4*       __restrict__ out)
{
    const int gwarp = (blockIdx.x * blockDim.x + threadIdx.x) >> 5;
    const int lane  = threadIdx.x & 31;
    if (gwarp >= BP * MI) return;

    const int bp = gwarp / MI;           // batch pair 0..3
    const int mi = gwarp - bp * MI;
    const int m0 = mi * 2;
    const int m1 = m0 + 1;
    const int b0 = bp * 2;
    const int b1 = b0 + 1;

    // warp-uniform indices / weights for both m (broadcast, L2-resident)
    const int  c00 = __ldg(cols + m0 * 3 + 0);
    const int  c01 = __ldg(cols + m0 * 3 + 1);
    const int  c02 = __ldg(cols + m0 * 3 + 2);
    const int  c10 = __ldg(cols + m1 * 3 + 0);
    const int  c11 = __ldg(cols + m1 * 3 + 1);
    const int  c12 = __ldg(cols + m1 * 3 + 2);
    const float v00 = __ldg(vals + m0 * 3 + 0);
    const float v01 = __ldg(vals + m0 * 3 + 1);
    const float v02 = __ldg(vals + m0 * 3 + 2);
    const float v10 = __ldg(vals + m1 * 3 + 0);
    const float v11 = __ldg(vals + m1 * 3 + 1);
    const float v12 = __ldg(vals + m1 * 3 + 2);

    const float4* xb0 = x + (size_t)b0 * N_DIM * C_VEC + lane;
    const float4* xb1 = x + (size_t)b1 * N_DIM * C_VEC + lane;

    // 12 independent 16B loads in flight, all 512B-row coalesced
    const float4 a00 = __ldg(xb0 + (size_t)c00 * C_VEC);
    const float4 a01 = __ldg(xb0 + (size_t)c01 * C_VEC);
    const float4 a02 = __ldg(xb0 + (size_t)c02 * C_VEC);
    const float4 a10 = __ldg(xb0 + (size_t)c10 * C_VEC);
    const float4 a11 = __ldg(xb0 + (size_t)c11 * C_VEC);
    const float4 a12 = __ldg(xb0 + (size_t)c12 * C_VEC);
    const float4 a20 = __ldg(xb1 + (size_t)c00 * C_VEC);
    const float4 a21 = __ldg(xb1 + (size_t)c01 * C_VEC);
    const float4 a22 = __ldg(xb1 + (size_t)c02 * C_VEC);
    const float4 a30 = __ldg(xb1 + (size_t)c10 * C_VEC);
    const float4 a31 = __ldg(xb1 + (size_t)c11 * C_VEC);
    const float4 a32 = __ldg(xb1 + (size_t)c12 * C_VEC);

    float4 r;
    // (b0, m0)
    r.x = v00 * a00.x + v01 * a01.x + v02 * a02.x;
    r.y = v00 * a00.y + v01 * a01.y + v02 * a02.y;
    r.z = v00 * a00.z + v01 * a01.z + v02 * a02.z;
    r.w = v00 * a00.w + v01 * a01.w + v02 * a02.w;
    stcs(out + ((size_t)b0 * M_DIM + m0) * C_VEC + lane, r);
    // (b0, m1)
    r.x = v10 * a10.x + v11 * a11.x + v12 * a12.x;
    r.y = v10 * a10.y + v11 * a11.y + v12 * a12.y;
    r.z = v10 * a10.z + v11 * a11.z + v12 * a12.z;
    r.w = v10 * a10.w + v11 * a11.w + v12 * a12.w;
    stcs(out + ((size_t)b0 * M_DIM + m1) * C_VEC + lane, r);
    // (b1, m0)
    r.x = v00 * a20.x + v01 * a21.x + v02 * a22.x;
    r.y = v00 * a20.y + v01 * a21.y + v02 * a22.y;
    r.z = v00 * a20.z + v01 * a21.z + v02 * a22.z;
    r.w = v00 * a20.w + v01 * a21.w + v02 * a22.w;
    stcs(out + ((size_t)b1 * M_DIM + m0) * C_VEC + lane, r);
    // (b1, m1)
    r.x = v10 * a30.x + v11 * a31.x + v12 * a32.x;
    r.y = v10 * a30.y + v11 * a31.y + v12 * a32.y;
    r.z = v10 * a30.z + v11 * a31.z + v12 * a32.z;
    r.w = v10 * a30.w + v11 * a31.w + v12 * a32.w;
    stcs(out + ((size_t)b1 * M_DIM + m1) * C_VEC + lane, r);
}

extern "C" void kernel_launch(void* const* d_in, const int* in_sizes, int n_in,
                              void* d_out, int out_size)
{
    const float4* x    = (const float4*)d_in[0];
    const int*    cols = (const int*)d_in[1];
    const float*  vals = (const float*)d_in[2];
    float4*       out  = (float4*)d_out;

    const int total_warps   = BP * MI;                // 50000
    const int threads       = 256;                    // 8 warps / block
    const int warps_per_blk = threads / 32;
    const int blocks        = (total_warps + warps_per_blk - 1) / warps_per_blk;

    mesh_sampling_kernel<<<blocks, threads>>>(x, cols, vals, out);
}